// round 6
// baseline (speedup 1.0000x reference)
#include <cuda_runtime.h>
#include <cuda_bf16.h>

#define N_NODES 50000
#define N_EDGES 800000
#define D 128
#define N_GRAPHS 128
#define OUT_DIM 16
#define SLOTS 64            // fixed adjacency slots per node (Poisson(16) max << 64)
#define WS 132              // padded k-stride for transposed weights (16B-aligned, conflict-free)

// Scratch (no cudaMalloc allowed)
__device__ float g_agg[N_NODES * D];
__device__ float g_hA[N_NODES * D];
__device__ float g_hB[N_NODES * D];
__device__ float g_sums[N_GRAPHS * D];
__device__ float g_cnt[N_GRAPHS];
__device__ int g_deg[N_NODES];
__device__ int g_adj[N_NODES * SLOTS];        // 12.8 MB
__device__ float g_WT[6 * D * WS];            // 6 transposed weight mats [c][k], padded

// ---------------------------------------------------------------------------
// Zero degrees + pool accumulators (one kernel)
// ---------------------------------------------------------------------------
__global__ void k_zero() {
    int i = blockIdx.x * blockDim.x + threadIdx.x;
    if (i < N_NODES) g_deg[i] = 0;
    if (i < N_GRAPHS * D) g_sums[i] = 0.f;
    if (i < N_GRAPHS) g_cnt[i] = 0.f;
}

// ---------------------------------------------------------------------------
// Weight transpose: WT[c*WS + k] = W[k*D + c].  One block per matrix.
// blockIdx.x = layer*2 + (0:rel, 1:root)
// ---------------------------------------------------------------------------
__global__ __launch_bounds__(128) void k_wt(const float* __restrict__ Wrel,
                                            const float* __restrict__ Wroot) {
    int m = blockIdx.x;
    int layer = m >> 1;
    const float* src = (m & 1) ? (Wroot + layer * D * D) : (Wrel + layer * D * D);
    float* dst = g_WT + m * D * WS;
    int c = threadIdx.x;
#pragma unroll 8
    for (int k = 0; k < D; k++)
        dst[c * WS + k] = src[k * D + c];   // coalesced read, strided write (tiny)
}

// ---------------------------------------------------------------------------
// Fill fixed-slot adjacency: adj[dst][p] = src
// ---------------------------------------------------------------------------
__global__ void k_fill(const int* __restrict__ ei) {
    int e = blockIdx.x * blockDim.x + threadIdx.x;
    if (e < N_EDGES) {
        int dst = ei[N_EDGES + e];
        int p = atomicAdd(&g_deg[dst], 1);
        if (p < SLOTS) g_adj[dst * SLOTS + p] = ei[e];
    }
}

// ---------------------------------------------------------------------------
// Gather: agg[n] = sum_{s in adj(n)} h[s].  One warp per node, lane = float4.
// ---------------------------------------------------------------------------
__global__ __launch_bounds__(256) void k_gather(const float* __restrict__ h) {
    int n = (blockIdx.x * blockDim.x + threadIdx.x) >> 5;
    if (n >= N_NODES) return;
    int lane = threadIdx.x & 31;
    int deg = g_deg[n];
    if (deg > SLOTS) deg = SLOTS;
    const int* adj = g_adj + n * SLOTS;
    float4 acc = make_float4(0.f, 0.f, 0.f, 0.f);
    int i = 0;
    for (; i + 4 <= deg; i += 4) {
        int s0 = adj[i], s1 = adj[i + 1], s2 = adj[i + 2], s3 = adj[i + 3];
        float4 v0 = *reinterpret_cast<const float4*>(h + (long long)s0 * D + lane * 4);
        float4 v1 = *reinterpret_cast<const float4*>(h + (long long)s1 * D + lane * 4);
        float4 v2 = *reinterpret_cast<const float4*>(h + (long long)s2 * D + lane * 4);
        float4 v3 = *reinterpret_cast<const float4*>(h + (long long)s3 * D + lane * 4);
        acc.x += v0.x + v1.x + v2.x + v3.x;
        acc.y += v0.y + v1.y + v2.y + v3.y;
        acc.z += v0.z + v1.z + v2.z + v3.z;
        acc.w += v0.w + v1.w + v2.w + v3.w;
    }
    for (; i < deg; i++) {
        int s = adj[i];
        float4 v = *reinterpret_cast<const float4*>(h + (long long)s * D + lane * 4);
        acc.x += v.x; acc.y += v.y; acc.z += v.z; acc.w += v.w;
    }
    *reinterpret_cast<float4*>(g_agg + (long long)n * D + lane * 4) = acc;
}

// ---------------------------------------------------------------------------
// Fused GraphConv GEMM, k-packed f32x2:
//   hout = relu( g_agg @ Wrel + hin @ Wroot + brel )
// acc[r][c] is f32x2 over (even k, odd k); horizontal add in epilogue.
// Weights pre-transposed in g_WT (stride WS), A/H tiles row-major.
// 64 rows/block, 256 threads: thread = 8 rows x 4 cols (cols tx, tx+32, +64, +96).
// ---------------------------------------------------------------------------
#define BM 64
#define GEMM_SMEM_FLOATS (2 * D * WS + 2 * BM * D + D)
#define GEMM_SMEM_BYTES (GEMM_SMEM_FLOATS * 4)

__device__ __forceinline__ void fma2(unsigned long long& acc,
                                     unsigned long long a,
                                     unsigned long long b) {
    asm("fma.rn.f32x2 %0, %1, %2, %0;" : "+l"(acc) : "l"(a), "l"(b));
}
__device__ __forceinline__ float2 unpack2(unsigned long long p) {
    unsigned int lo, hi;
    asm("mov.b64 {%0, %1}, %2;" : "=r"(lo), "=r"(hi) : "l"(p));
    return make_float2(__uint_as_float(lo), __uint_as_float(hi));
}

__global__ __launch_bounds__(256, 1) void k_gemm(const float* __restrict__ hin,
                                                 const float* __restrict__ WTrel,
                                                 const float* __restrict__ brel,
                                                 const float* __restrict__ WTroot,
                                                 float* __restrict__ hout) {
    extern __shared__ float smem[];
    float* sWr = smem;                   // 128*WS
    float* sWo = smem + D * WS;          // 128*WS
    float* sA = smem + 2 * D * WS;       // 64*128
    float* sH = sA + BM * D;             // 64*128
    float* sb = sH + BM * D;             // 128

    int tid = threadIdx.x;
    int tx = tid & 31;
    int ty = tid >> 5;
    int row0 = blockIdx.x * BM;

    // Load transposed weights (contiguous, padded region is dead data)
    {
        const float4* wr4 = reinterpret_cast<const float4*>(WTrel);
        const float4* wo4 = reinterpret_cast<const float4*>(WTroot);
        float4* sr4 = reinterpret_cast<float4*>(sWr);
        float4* so4 = reinterpret_cast<float4*>(sWo);
        const int n4 = D * WS / 4;       // 4224
        for (int i = tid; i < n4; i += 256) {
            sr4[i] = wr4[i];
            so4[i] = wo4[i];
        }
        if (tid < 32) reinterpret_cast<float4*>(sb)[tid] =
            reinterpret_cast<const float4*>(brel)[tid];
    }

    // Load A (agg) and H tiles, zero-padded past N_NODES
    {
        float4* sA4 = reinterpret_cast<float4*>(sA);
        float4* sH4 = reinterpret_cast<float4*>(sH);
#pragma unroll
        for (int i = 0; i < (BM * D / 4) / 256; i++) {
            int idx = i * 256 + tid;
            int r = idx >> 5;
            int row = row0 + r;
            if (row < N_NODES) {
                sA4[idx] = reinterpret_cast<const float4*>(g_agg)[row * 32 + (idx & 31)];
                sH4[idx] = reinterpret_cast<const float4*>(hin)[(long long)row * 32 + (idx & 31)];
            } else {
                sA4[idx] = make_float4(0.f, 0.f, 0.f, 0.f);
                sH4[idx] = make_float4(0.f, 0.f, 0.f, 0.f);
            }
        }
    }
    __syncthreads();

    unsigned long long acc[8][4];
#pragma unroll
    for (int r = 0; r < 8; r++)
#pragma unroll
        for (int c = 0; c < 4; c++) acc[r][c] = 0ull;

#pragma unroll 4
    for (int kb = 0; kb < D; kb += 4) {
        // Weights: {W[kb],W[kb+1]} and {W[kb+2],W[kb+3]} for each of 4 cols
        ulonglong2 wr[4], wo[4];
#pragma unroll
        for (int c = 0; c < 4; c++) {
            wr[c] = *reinterpret_cast<const ulonglong2*>(&sWr[(tx + c * 32) * WS + kb]);
            wo[c] = *reinterpret_cast<const ulonglong2*>(&sWo[(tx + c * 32) * WS + kb]);
        }
#pragma unroll
        for (int r = 0; r < 8; r++) {
            ulonglong2 aP = *reinterpret_cast<const ulonglong2*>(&sA[(ty * 8 + r) * D + kb]);
            ulonglong2 hP = *reinterpret_cast<const ulonglong2*>(&sH[(ty * 8 + r) * D + kb]);
#pragma unroll
            for (int c = 0; c < 4; c++) {
                fma2(acc[r][c], aP.x, wr[c].x);
                fma2(acc[r][c], aP.y, wr[c].y);
                fma2(acc[r][c], hP.x, wo[c].x);
                fma2(acc[r][c], hP.y, wo[c].y);
            }
        }
    }

    // Epilogue: horizontal add (even-k + odd-k), bias, relu
#pragma unroll
    for (int r = 0; r < 8; r++) {
        int row = row0 + ty * 8 + r;
        if (row < N_NODES) {
#pragma unroll
            for (int c = 0; c < 4; c++) {
                float2 p = unpack2(acc[r][c]);
                float v = fmaxf(p.x + p.y + sb[tx + c * 32], 0.f);
                hout[(long long)row * D + tx + c * 32] = v;   // coalesced STG.32
            }
        }
    }
}

// ---------------------------------------------------------------------------
// Pool + head
// ---------------------------------------------------------------------------
#define NODES_PER_WARP 4
__global__ __launch_bounds__(256) void k_pool(const float* __restrict__ h,
                                              const int* __restrict__ batch) {
    int gwarp = (blockIdx.x * blockDim.x + threadIdx.x) >> 5;
    int lane = threadIdx.x & 31;
#pragma unroll
    for (int i = 0; i < NODES_PER_WARP; i++) {
        int n = gwarp * NODES_PER_WARP + i;
        if (n >= N_NODES) return;
        int g = batch[n];
        const float4 v = *reinterpret_cast<const float4*>(h + (long long)n * D + lane * 4);
        float* dp = g_sums + g * D + lane * 4;
        asm volatile("red.global.add.v4.f32 [%0], {%1,%2,%3,%4};"
                     :: "l"(dp), "f"(v.x), "f"(v.y), "f"(v.z), "f"(v.w)
                     : "memory");
        if (lane == 0) atomicAdd(&g_cnt[g], 1.0f);
    }
}

__global__ __launch_bounds__(128) void k_head(const float* __restrict__ W1,
                                              const float* __restrict__ b1,
                                              const float* __restrict__ W2,
                                              const float* __restrict__ b2,
                                              float* __restrict__ out) {
    __shared__ float pooled[D];
    __shared__ float t[D];
    int g = blockIdx.x;
    int tid = threadIdx.x;
    float cnt = fmaxf(g_cnt[g], 1.0f);
    pooled[tid] = g_sums[g * D + tid] / cnt;
    __syncthreads();

    float acc = b1[tid];
#pragma unroll 8
    for (int k = 0; k < D; k++) acc += pooled[k] * W1[k * D + tid];
    t[tid] = acc;
    __syncthreads();

    if (tid < OUT_DIM) {
        float o = b2[tid];
#pragma unroll 8
        for (int k = 0; k < D; k++) o += t[k] * W2[k * OUT_DIM + tid];
        out[g * OUT_DIM + tid] = o;
    }
}

// ---------------------------------------------------------------------------
// Launch sequence (graph-capturable: kernel launches only)
// ---------------------------------------------------------------------------
extern "C" void kernel_launch(void* const* d_in, const int* in_sizes, int n_in,
                              void* d_out, int out_size) {
    const float* x = (const float*)d_in[0];
    const int* ei = (const int*)d_in[1];      // int32 (JAX x64 disabled)
    const int* batch = (const int*)d_in[2];   // int32
    const float* Wrel = (const float*)d_in[3];
    const float* brel = (const float*)d_in[4];
    const float* Wroot = (const float*)d_in[5];
    const float* W1 = (const float*)d_in[6];
    const float* b1 = (const float*)d_in[7];
    const float* W2 = (const float*)d_in[8];
    const float* b2 = (const float*)d_in[9];
    float* out = (float*)d_out;

    cudaFuncSetAttribute(k_gemm, cudaFuncAttributeMaxDynamicSharedMemorySize,
                         GEMM_SMEM_BYTES);

    float* hA;
    float* hB;
    float* wt;
    cudaGetSymbolAddress((void**)&hA, g_hA);
    cudaGetSymbolAddress((void**)&hB, g_hB);
    cudaGetSymbolAddress((void**)&wt, g_WT);

    const int edge_blocks = (N_EDGES + 255) / 256;
    const int gemm_blocks = (N_NODES + BM - 1) / BM;
    const int gather_blocks = (N_NODES + 7) / 8;
    const int pool_blocks = (N_NODES + 8 * NODES_PER_WARP - 1) / (8 * NODES_PER_WARP);

    // Setup: zero deg+pool, transpose weights, fill adjacency
    k_zero<<<(N_NODES + 255) / 256, 256>>>();
    k_wt<<<6, 128>>>(Wrel, Wroot);
    k_fill<<<edge_blocks, 256>>>(ei);

    // Layer 0: x -> hB
    k_gather<<<gather_blocks, 256>>>(x);
    k_gemm<<<gemm_blocks, 256, GEMM_SMEM_BYTES>>>(x, wt + 0 * D * WS, brel,
                                                  wt + 1 * D * WS, hB);
    // Layer 1: hB -> hA
    k_gather<<<gather_blocks, 256>>>(hB);
    k_gemm<<<gemm_blocks, 256, GEMM_SMEM_BYTES>>>(hB, wt + 2 * D * WS, brel + D,
                                                  wt + 3 * D * WS, hA);
    // Layer 2: hA -> hB
    k_gather<<<gather_blocks, 256>>>(hA);
    k_gemm<<<gemm_blocks, 256, GEMM_SMEM_BYTES>>>(hA, wt + 4 * D * WS, brel + 2 * D,
                                                  wt + 5 * D * WS, hB);

    // Pool + head
    k_pool<<<pool_blocks, 256>>>(hB, batch);
    k_head<<<N_GRAPHS, 128>>>(W1, b1, W2, b2, out);
}

// round 8
// speedup vs baseline: 1.7068x; 1.7068x over previous
#include <cuda_runtime.h>
#include <cuda_bf16.h>
#include <cstdint>

#define N_NODES 50000
#define N_EDGES 800000
#define D 128
#define N_GRAPHS 128
#define OUT_DIM 16
#define SLOTS 64            // fixed adjacency slots per node (Poisson(16), P(>64)~1e-20)
#define STRA 136            // bf16 row stride for MMA tiles (272B: 16B-aligned, conflict-free)
#define IMG (128 * STRA)    // 17408 bf16 elems per 128x128 tile image (34816 B)

// ---------------------------------------------------------------------------
// Scratch (no cudaMalloc allowed)
// ---------------------------------------------------------------------------
__device__ float g_agg[N_NODES * D];
__device__ float g_hA[N_NODES * D];
__device__ float g_hB[N_NODES * D];
__device__ float g_sums[N_GRAPHS * D];
__device__ float g_cnt[N_GRAPHS];
__device__ int g_deg[N_NODES];
__device__ int g_adj[N_NODES * SLOTS];          // 12.8 MB
// Pre-split bf16 weights, transposed to [n][k], stride STRA.
// Per layer: [relHi][relLo][rootHi][rootLo], each IMG bf16.
__device__ __align__(16) __nv_bfloat16 g_Wsplit[3 * 4 * IMG];

// ---------------------------------------------------------------------------
// Helpers
// ---------------------------------------------------------------------------
__device__ __forceinline__ uint32_t smem_u32(const void* p) {
    uint32_t a;
    asm("{ .reg .u64 t; cvta.to.shared.u64 t, %1; cvt.u32.u64 %0, t; }"
        : "=r"(a) : "l"(p));
    return a;
}
__device__ __forceinline__ uint32_t pack_bf16(float lo, float hi) {
    uint32_t r;   // upper half <- hi, lower half <- lo
    asm("cvt.rn.bf16x2.f32 %0, %1, %2;" : "=r"(r) : "f"(hi), "f"(lo));
    return r;
}
__device__ __forceinline__ void ldsm4(uint32_t* r, uint32_t addr) {
    asm volatile("ldmatrix.sync.aligned.m8n8.x4.shared.b16 {%0,%1,%2,%3}, [%4];"
                 : "=r"(r[0]), "=r"(r[1]), "=r"(r[2]), "=r"(r[3]) : "r"(addr));
}
__device__ __forceinline__ void mma16816(float* c, const uint32_t* a,
                                         uint32_t b0, uint32_t b1) {
    asm volatile(
        "mma.sync.aligned.m16n8k16.row.col.f32.bf16.bf16.f32 "
        "{%0,%1,%2,%3}, {%4,%5,%6,%7}, {%8,%9}, {%0,%1,%2,%3};"
        : "+f"(c[0]), "+f"(c[1]), "+f"(c[2]), "+f"(c[3])
        : "r"(a[0]), "r"(a[1]), "r"(a[2]), "r"(a[3]), "r"(b0), "r"(b1));
}

// ---------------------------------------------------------------------------
// Setup kernels
// ---------------------------------------------------------------------------
__global__ void k_zero() {
    int i = blockIdx.x * blockDim.x + threadIdx.x;
    if (i < N_NODES) g_deg[i] = 0;
    if (i < N_GRAPHS * D) g_sums[i] = 0.f;
    if (i < N_GRAPHS) g_cnt[i] = 0.f;
}

__global__ void k_fill(const int* __restrict__ ei) {
    int e = blockIdx.x * blockDim.x + threadIdx.x;
    if (e < N_EDGES) {
        int dst = ei[N_EDGES + e];
        int p = atomicAdd(&g_deg[dst], 1);
        if (p < SLOTS) g_adj[dst * SLOTS + p] = ei[e];
    }
}

// Split W (k-major [k][n]) into bf16 hi/lo, transposed to [n][k], stride STRA.
// blockIdx.x = layer*2 + isroot
__global__ __launch_bounds__(256) void k_wprep(const float* __restrict__ Wrel,
                                               const float* __restrict__ Wroot) {
    int m = blockIdx.x;
    int layer = m >> 1;
    int isroot = m & 1;
    const float* W = (isroot ? Wroot : Wrel) + layer * D * D;
    __nv_bfloat16* hiP = g_Wsplit + (layer * 4 + isroot * 2) * IMG;
    __nv_bfloat16* loP = hiP + IMG;
    for (int i = threadIdx.x; i < D * D; i += 256) {
        int n = i & 127;
        int k = i >> 7;
        float w = W[k * D + n];                     // coalesced in n
        __nv_bfloat16 h = __float2bfloat16(w);
        __nv_bfloat16 l = __float2bfloat16(w - __bfloat162float(h));
        hiP[n * STRA + k] = h;
        loP[n * STRA + k] = l;
    }
}

// ---------------------------------------------------------------------------
// Gather: agg[n] = sum_{s in adj(n)} h[s].  One warp per node (29.5us measured)
// ---------------------------------------------------------------------------
__global__ __launch_bounds__(256) void k_gather(const float* __restrict__ h) {
    int n = (blockIdx.x * blockDim.x + threadIdx.x) >> 5;
    if (n >= N_NODES) return;
    int lane = threadIdx.x & 31;
    int deg = g_deg[n];
    if (deg > SLOTS) deg = SLOTS;
    const int* adj = g_adj + n * SLOTS;
    float4 acc = make_float4(0.f, 0.f, 0.f, 0.f);
    int i = 0;
    for (; i + 4 <= deg; i += 4) {
        int s0 = adj[i], s1 = adj[i + 1], s2 = adj[i + 2], s3 = adj[i + 3];
        float4 v0 = *reinterpret_cast<const float4*>(h + (size_t)s0 * D + lane * 4);
        float4 v1 = *reinterpret_cast<const float4*>(h + (size_t)s1 * D + lane * 4);
        float4 v2 = *reinterpret_cast<const float4*>(h + (size_t)s2 * D + lane * 4);
        float4 v3 = *reinterpret_cast<const float4*>(h + (size_t)s3 * D + lane * 4);
        acc.x += v0.x + v1.x + v2.x + v3.x;
        acc.y += v0.y + v1.y + v2.y + v3.y;
        acc.z += v0.z + v1.z + v2.z + v3.z;
        acc.w += v0.w + v1.w + v2.w + v3.w;
    }
    for (; i < deg; i++) {
        int s = adj[i];
        float4 v = *reinterpret_cast<const float4*>(h + (size_t)s * D + lane * 4);
        acc.x += v.x; acc.y += v.y; acc.z += v.z; acc.w += v.w;
    }
    *reinterpret_cast<float4*>(g_agg + (size_t)n * D + lane * 4) = acc;
}

// ---------------------------------------------------------------------------
// HMMA GraphConv GEMM (mma.sync bf16, split hi/lo, 3 products):
//   hout[128 rows] = relu( agg@Wrel + hin@Wroot + b )
// CTA: 256 thr / 8 warps, each warp 32m x 64n.
// SMEM bytes: W images 4*34816 | Ahi 34816 | Alo 34816 | bias 512
// ---------------------------------------------------------------------------
#define SMB_AHI  139264
#define SMB_ALO  174080
#define SMB_BIAS 208896
#define SM_TOTAL 209408

// Convert 128 fp32 rows -> bf16 hi/lo tiles (stride STRA)
__device__ __forceinline__ void convA(const float* __restrict__ src, int row0,
                                      char* smem) {
    char* hiP = smem + SMB_AHI;
    char* loP = smem + SMB_ALO;
#pragma unroll
    for (int it = 0; it < 16; it++) {
        int idx = it * 256 + threadIdx.x;
        int row = idx >> 5;                 // 0..127
        int c4 = (idx & 31) * 4;            // k offset, multiple of 4
        int grow = row0 + row;
        float4 v = make_float4(0.f, 0.f, 0.f, 0.f);
        if (grow < N_NODES)
            v = *reinterpret_cast<const float4*>(src + (size_t)grow * D + c4);
        uint32_t h0 = pack_bf16(v.x, v.y);
        uint32_t h1 = pack_bf16(v.z, v.w);
        float r0 = v.x - __uint_as_float(h0 << 16);
        float r1 = v.y - __uint_as_float(h0 & 0xFFFF0000u);
        float r2 = v.z - __uint_as_float(h1 << 16);
        float r3 = v.w - __uint_as_float(h1 & 0xFFFF0000u);
        uint32_t l0 = pack_bf16(r0, r1);
        uint32_t l1 = pack_bf16(r2, r3);
        uint32_t off = (uint32_t)(row * (STRA * 2) + c4 * 2);
        *reinterpret_cast<uint2*>(hiP + off) = make_uint2(h0, h1);
        *reinterpret_cast<uint2*>(loP + off) = make_uint2(l0, l1);
    }
}

// One K=128 pass: c += Ahi*(Whi+Wlo) + Alo*Whi   (A tiles in smem, W image wsel)
__device__ __forceinline__ void mma_pass(float c[2][8][4], uint32_t sbase,
                                         int wimg, int mrow0, int ncol0, int lane) {
    uint32_t aHiBase = sbase + SMB_AHI;
    uint32_t aLoBase = sbase + SMB_ALO;
    uint32_t wHiBase = sbase + (uint32_t)(wimg * 34816);
    uint32_t wLoBase = wHiBase + 34816;
    // per-lane ldmatrix address components
    int arow = (lane & 7) + ((lane >> 3) & 1) * 8;   // A: row within 16
    int akc = ((lane >> 4) & 1) * 8;                 // A: k chunk
    int bn = (lane & 7) + ((lane >> 4) & 1) * 8;     // B: n within 16
    int bkc = ((lane >> 3) & 1) * 8;                 // B: k chunk

#pragma unroll
    for (int ks = 0; ks < 8; ks++) {
        int k0 = ks * 16;
        uint32_t aHi[2][4], aLo[2][4];
#pragma unroll
        for (int mt = 0; mt < 2; mt++) {
            uint32_t off = (uint32_t)((mrow0 + mt * 16 + arow) * (STRA * 2) +
                                      (k0 + akc) * 2);
            ldsm4(aHi[mt], aHiBase + off);
            ldsm4(aLo[mt], aLoBase + off);
        }
#pragma unroll
        for (int np = 0; np < 4; np++) {
            uint32_t woff = (uint32_t)((ncol0 + np * 16 + bn) * (STRA * 2) +
                                       (k0 + bkc) * 2);
            uint32_t b[4];
            ldsm4(b, wHiBase + woff);                 // b0/b1 of 2 n-tiles (hi)
#pragma unroll
            for (int mt = 0; mt < 2; mt++) {
                mma16816(c[mt][np * 2], aHi[mt], b[0], b[1]);
                mma16816(c[mt][np * 2 + 1], aHi[mt], b[2], b[3]);
                mma16816(c[mt][np * 2], aLo[mt], b[0], b[1]);
                mma16816(c[mt][np * 2 + 1], aLo[mt], b[2], b[3]);
            }
            ldsm4(b, wLoBase + woff);                 // lo image
#pragma unroll
            for (int mt = 0; mt < 2; mt++) {
                mma16816(c[mt][np * 2], aHi[mt], b[0], b[1]);
                mma16816(c[mt][np * 2 + 1], aHi[mt], b[2], b[3]);
            }
        }
    }
}

__global__ __launch_bounds__(256, 1)
void k_gemm_mma(const float* __restrict__ hin,
                const __nv_bfloat16* __restrict__ wlayer,  // 4 images
                const float* __restrict__ bias,
                float* __restrict__ hout) {
    extern __shared__ char smem[];
    int tid = threadIdx.x;
    int w = tid >> 5;
    int lane = tid & 31;
    int row0 = blockIdx.x * 128;
    int mrow0 = (w & 3) * 32;
    int ncol0 = (w >> 2) * 64;
    uint32_t sbase = smem_u32(smem);

    // Weights: contiguous copy of 4 pre-swizzled images (139264 B)
    {
        const float4* s4 = reinterpret_cast<const float4*>(wlayer);
        float4* d4 = reinterpret_cast<float4*>(smem);
#pragma unroll
        for (int i = 0; i < 34; i++) d4[i * 256 + tid] = s4[i * 256 + tid];
    }
    if (tid < 128) ((float*)(smem + SMB_BIAS))[tid] = bias[tid];

    float c[2][8][4];
#pragma unroll
    for (int mt = 0; mt < 2; mt++)
#pragma unroll
        for (int nt = 0; nt < 8; nt++)
#pragma unroll
            for (int i = 0; i < 4; i++) c[mt][nt][i] = 0.f;

    // Pass 0: agg @ Wrel
    convA(g_agg, row0, smem);
    __syncthreads();
    mma_pass(c, sbase, 0, mrow0, ncol0, lane);
    __syncthreads();
    // Pass 1: hin @ Wroot
    convA(hin, row0, smem);
    __syncthreads();
    mma_pass(c, sbase, 2, mrow0, ncol0, lane);

    // Epilogue: bias + relu, direct stores (float2 per fragment row)
    const float* sb = (const float*)(smem + SMB_BIAS);
    int g = lane >> 2;
    int t = lane & 3;
#pragma unroll
    for (int mt = 0; mt < 2; mt++) {
#pragma unroll
        for (int nt = 0; nt < 8; nt++) {
            int col = ncol0 + nt * 8 + t * 2;
            float b0 = sb[col], b1 = sb[col + 1];
            int r0 = row0 + mrow0 + mt * 16 + g;
            if (r0 < N_NODES) {
                float2 v;
                v.x = fmaxf(c[mt][nt][0] + b0, 0.f);
                v.y = fmaxf(c[mt][nt][1] + b1, 0.f);
                *reinterpret_cast<float2*>(hout + (size_t)r0 * D + col) = v;
            }
            int r1 = r0 + 8;
            if (r1 < N_NODES) {
                float2 v;
                v.x = fmaxf(c[mt][nt][2] + b0, 0.f);
                v.y = fmaxf(c[mt][nt][3] + b1, 0.f);
                *reinterpret_cast<float2*>(hout + (size_t)r1 * D + col) = v;
            }
        }
    }
}

// ---------------------------------------------------------------------------
// Pool + head
// ---------------------------------------------------------------------------
#define NODES_PER_WARP 4
__global__ __launch_bounds__(256) void k_pool(const float* __restrict__ h,
                                              const int* __restrict__ batch) {
    int gwarp = (blockIdx.x * blockDim.x + threadIdx.x) >> 5;
    int lane = threadIdx.x & 31;
#pragma unroll
    for (int i = 0; i < NODES_PER_WARP; i++) {
        int n = gwarp * NODES_PER_WARP + i;
        if (n >= N_NODES) return;
        int g = batch[n];
        const float4 v = *reinterpret_cast<const float4*>(h + (size_t)n * D + lane * 4);
        float* dp = g_sums + g * D + lane * 4;
        asm volatile("red.global.add.v4.f32 [%0], {%1,%2,%3,%4};"
                     :: "l"(dp), "f"(v.x), "f"(v.y), "f"(v.z), "f"(v.w)
                     : "memory");
        if (lane == 0) atomicAdd(&g_cnt[g], 1.0f);
    }
}

__global__ __launch_bounds__(128) void k_head(const float* __restrict__ W1,
                                              const float* __restrict__ b1,
                                              const float* __restrict__ W2,
                                              const float* __restrict__ b2,
                                              float* __restrict__ out) {
    __shared__ float pooled[D];
    __shared__ float t[D];
    int g = blockIdx.x;
    int tid = threadIdx.x;
    float cnt = fmaxf(g_cnt[g], 1.0f);
    pooled[tid] = g_sums[g * D + tid] / cnt;
    __syncthreads();

    float acc = b1[tid];
#pragma unroll 8
    for (int k = 0; k < D; k++) acc += pooled[k] * W1[k * D + tid];
    t[tid] = acc;
    __syncthreads();

    if (tid < OUT_DIM) {
        float o = b2[tid];
#pragma unroll 8
        for (int k = 0; k < D; k++) o += t[k] * W2[k * OUT_DIM + tid];
        out[g * OUT_DIM + tid] = o;
    }
}

// ---------------------------------------------------------------------------
// Launch sequence (graph-capturable: kernel launches only)
// ---------------------------------------------------------------------------
extern "C" void kernel_launch(void* const* d_in, const int* in_sizes, int n_in,
                              void* d_out, int out_size) {
    const float* x = (const float*)d_in[0];
    const int* ei = (const int*)d_in[1];      // int32 (JAX x64 disabled)
    const int* batch = (const int*)d_in[2];   // int32
    const float* Wrel = (const float*)d_in[3];
    const float* brel = (const float*)d_in[4];
    const float* Wroot = (const float*)d_in[5];
    const float* W1 = (const float*)d_in[6];
    const float* b1 = (const float*)d_in[7];
    const float* W2 = (const float*)d_in[8];
    const float* b2 = (const float*)d_in[9];
    float* out = (float*)d_out;

    cudaFuncSetAttribute(k_gemm_mma, cudaFuncAttributeMaxDynamicSharedMemorySize,
                         SM_TOTAL);

    float* hA;
    float* hB;
    __nv_bfloat16* wsp;
    cudaGetSymbolAddress((void**)&hA, g_hA);
    cudaGetSymbolAddress((void**)&hB, g_hB);
    cudaGetSymbolAddress((void**)&wsp, g_Wsplit);

    const int edge_blocks = (N_EDGES + 255) / 256;
    const int gemm_blocks = (N_NODES + 127) / 128;   // 391
    const int gather_blocks = (N_NODES + 7) / 8;
    const int pool_blocks = (N_NODES + 8 * NODES_PER_WARP - 1) / (8 * NODES_PER_WARP);

    // Setup
    k_zero<<<(N_NODES + 255) / 256, 256>>>();
    k_wprep<<<6, 256>>>(Wrel, Wroot);
    k_fill<<<edge_blocks, 256>>>(ei);

    // Layer 0: x -> hB
    k_gather<<<gather_blocks, 256>>>(x);
    k_gemm_mma<<<gemm_blocks, 256, SM_TOTAL>>>(x, wsp + 0 * 4 * IMG, brel, hB);
    // Layer 1: hB -> hA
    k_gather<<<gather_blocks, 256>>>(hB);
    k_gemm_mma<<<gemm_blocks, 256, SM_TOTAL>>>(hB, wsp + 1 * 4 * IMG, brel + D, hA);
    // Layer 2: hA -> hB
    k_gather<<<gather_blocks, 256>>>(hA);
    k_gemm_mma<<<gemm_blocks, 256, SM_TOTAL>>>(hA, wsp + 2 * 4 * IMG, brel + 2 * D, hB);

    // Pool + head
    k_pool<<<pool_blocks, 256>>>(hB, batch);
    k_head<<<N_GRAPHS, 128>>>(W1, b1, W2, b2, out);
}